// round 7
// baseline (speedup 1.0000x reference)
#include <cuda_runtime.h>
#include <cuda_bf16.h>

// BatchHardTripletLoss: B=4096, D=128, margin=0.3
// loss = mean over valid rows of relu(max_pos_dist - min_neg_dist + margin)
//
//  k0: init per-row accumulators (hp=0, hn=+inf), zero hist, detect label dtype
//  k1: per-row squared norms (1 warp/row) + label histogram
//  k2: tiled fp32 GEMM (64x64 tiles, 4x4 micro-tile), B-tile register-staged
//      software pipeline; fused epilogue does masked max/min on SQUARED
//      distances (sqrt is monotone -> deferred), merged via bitwise
//      atomicMax/Min (valid: all values >= 0 so uint order == float order).
//  k3: single-block reduce: per-row sqrt + validity + mean.

#define BSZ   4096
#define DM    128
#define NCLS  512
#define BM    64
#define BN    64
#define STR   68          // padded smem stride (floats); keeps 16B alignment
#define NSLAB 8           // column slabs -> grid.y
#define MARGIN 0.3f

__device__ unsigned g_hp[BSZ];     // max positive sq-dist (float bits, >=0)
__device__ unsigned g_hn[BSZ];     // min negative sq-dist (float bits, >=0)
__device__ float    g_norms[BSZ];
__device__ int      g_hist[NCLS];
__device__ int      g_lab64;       // 1 if labels are int64, 0 if int32

__device__ __forceinline__ int load_label(const void* lab, int i) {
    if (g_lab64) return (int)((const long long*)lab)[i];
    return ((const int*)lab)[i];
}

__global__ void k0_init(const void* __restrict__ lab) {
    int i = blockIdx.x * blockDim.x + threadIdx.x;
    if (i < BSZ) { g_hp[i] = 0u; g_hn[i] = 0x7f800000u; }
    if (i < NCLS) g_hist[i] = 0;
    if (i == 0) {
        // int64 labels (values 0..511, nonneg) -> high 32-bit words all 0.
        // For random int32 labels, 64 consecutive odd words all-zero is
        // probabilistically impossible.
        const int* w = (const int*)lab;
        int all0 = 1;
        #pragma unroll
        for (int j = 0; j < 64; j++) all0 &= (w[2 * j + 1] == 0);
        g_lab64 = all0;
    }
}

__global__ void k1_norm_hist(const float* __restrict__ emb, const void* __restrict__ lab) {
    int warp = (blockIdx.x * blockDim.x + threadIdx.x) >> 5;
    int lane = threadIdx.x & 31;
    if (warp >= BSZ) return;
    float4 v = ((const float4*)(emb + (size_t)warp * DM))[lane];
    float s = v.x * v.x + v.y * v.y + v.z * v.z + v.w * v.w;
    #pragma unroll
    for (int o = 16; o; o >>= 1) s += __shfl_xor_sync(0xffffffffu, s, o);
    if (lane == 0) {
        g_norms[warp] = s;
        atomicAdd(&g_hist[load_label(lab, warp)], 1);
    }
}

__global__ void __launch_bounds__(256, 2)
k2_gemm_minmax(const float* __restrict__ emb, const void* __restrict__ lab) {
    extern __shared__ float sm[];
    float* As = sm;                   // [DM][STR] transposed A tile
    float* Bs = As + DM * STR;        // [DM][STR] transposed B tile
    float* cn = Bs + DM * STR;        // [BN] col norms
    int*   cl = (int*)(cn + BN);      // [BN] col labels

    const int tid = threadIdx.x;
    const int ty = tid >> 4;          // 0..15 (row group)
    const int tx = tid & 15;          // 0..15 (col group)
    const int row0 = blockIdx.x * BM;
    const int col_base = blockIdx.y * (BSZ / NSLAB);

    // per-thread tile-load coordinates (8 chunks of 256 threads)
    const int lr  = tid >> 5;         // base row for chunk 0 (rows advance by 8/chunk)
    const int lk4 = tid & 31;

    // ---- load A tile (64 rows x 128 k) transposed into As[k][m] ----
    #pragma unroll
    for (int i = 0; i < 8; i++) {
        int r = lr + i * 8;
        float4 v = ((const float4*)(emb + (size_t)(row0 + r) * DM))[lk4];
        As[(lk4 * 4 + 0) * STR + r] = v.x;
        As[(lk4 * 4 + 1) * STR + r] = v.y;
        As[(lk4 * 4 + 2) * STR + r] = v.z;
        As[(lk4 * 4 + 3) * STR + r] = v.w;
    }

    float rn[4];
    int   rl[4];
    #pragma unroll
    for (int i = 0; i < 4; i++) {
        int r = row0 + ty * 4 + i;
        rn[i] = g_norms[r];
        rl[i] = load_label(lab, r);
    }

    const float INF = __int_as_float(0x7f800000);
    float pmax[4] = {0.f, 0.f, 0.f, 0.f};
    float nmin[4] = {INF, INF, INF, INF};

    const int ntiles = (BSZ / NSLAB) / BN;

    // ---- stage tile 0 of B in registers ----
    float4 stage[8];
    float  cns = 0.f;
    int    cls = 0;
    {
        int c0 = col_base;
        #pragma unroll
        for (int i = 0; i < 8; i++) {
            int r = lr + i * 8;
            stage[i] = ((const float4*)(emb + (size_t)(c0 + r) * DM))[lk4];
        }
        if (tid < BN) { cns = g_norms[c0 + tid]; cls = load_label(lab, c0 + tid); }
    }

    for (int ct = 0; ct < ntiles; ct++) {
        __syncthreads();   // As ready (first iter) / Bs consumers done (later)

        // commit staged tile to smem
        #pragma unroll
        for (int i = 0; i < 8; i++) {
            int r = lr + i * 8;
            Bs[(lk4 * 4 + 0) * STR + r] = stage[i].x;
            Bs[(lk4 * 4 + 1) * STR + r] = stage[i].y;
            Bs[(lk4 * 4 + 2) * STR + r] = stage[i].z;
            Bs[(lk4 * 4 + 3) * STR + r] = stage[i].w;
        }
        if (tid < BN) { cn[tid] = cns; cl[tid] = cls; }
        __syncthreads();

        // prefetch next tile while the FMA block runs (L2 latency hidden)
        if (ct + 1 < ntiles) {
            int c1 = col_base + (ct + 1) * BN;
            #pragma unroll
            for (int i = 0; i < 8; i++) {
                int r = lr + i * 8;
                stage[i] = ((const float4*)(emb + (size_t)(c1 + r) * DM))[lk4];
            }
            if (tid < BN) { cns = g_norms[c1 + tid]; cls = load_label(lab, c1 + tid); }
        }

        float acc[4][4] = {};
        #pragma unroll 8
        for (int k = 0; k < DM; k++) {
            float4 a = *(const float4*)&As[k * STR + ty * 4];
            float4 b = *(const float4*)&Bs[k * STR + tx * 4];
            acc[0][0] += a.x * b.x; acc[0][1] += a.x * b.y; acc[0][2] += a.x * b.z; acc[0][3] += a.x * b.w;
            acc[1][0] += a.y * b.x; acc[1][1] += a.y * b.y; acc[1][2] += a.y * b.z; acc[1][3] += a.y * b.w;
            acc[2][0] += a.z * b.x; acc[2][1] += a.z * b.y; acc[2][2] += a.z * b.z; acc[2][3] += a.z * b.w;
            acc[3][0] += a.w * b.x; acc[3][1] += a.w * b.y; acc[3][2] += a.w * b.z; acc[3][3] += a.w * b.w;
        }

        // fused epilogue on squared distances (clamped >= 0)
        #pragma unroll
        for (int j = 0; j < 4; j++) {
            float cnj = cn[tx * 4 + j];
            int   clj = cl[tx * 4 + j];
            #pragma unroll
            for (int i = 0; i < 4; i++) {
                float sq = fmaxf(rn[i] + cnj - 2.0f * acc[i][j], 0.0f);
                if (rl[i] == clj) pmax[i] = fmaxf(pmax[i], sq);   // self-pair sq~0: harmless
                else              nmin[i] = fminf(nmin[i], sq);
            }
        }
    }

    // reduce across the 16 threads (tx) sharing each row group
    #pragma unroll
    for (int i = 0; i < 4; i++) {
        float p = pmax[i], n = nmin[i];
        #pragma unroll
        for (int o = 1; o < 16; o <<= 1) {
            p = fmaxf(p, __shfl_xor_sync(0xffffffffu, p, o));
            n = fminf(n, __shfl_xor_sync(0xffffffffu, n, o));
        }
        if (tx == 0) {
            int r = row0 + ty * 4 + i;
            atomicMax(&g_hp[r], __float_as_uint(p));
            atomicMin(&g_hn[r], __float_as_uint(n));
        }
    }
}

__global__ void k3_reduce(const void* __restrict__ lab, float* __restrict__ out) {
    __shared__ float ssum[512];
    __shared__ float scnt[512];
    int tid = threadIdx.x;
    float sum = 0.f, cnt = 0.f;
    for (int r = tid; r < BSZ; r += 512) {
        int h = g_hist[load_label(lab, r)];
        bool valid = (h > 1) && (h < BSZ);
        if (valid) {
            float hp = __uint_as_float(g_hp[r]);
            float hn = __uint_as_float(g_hn[r]);
            float dp = sqrtf(fmaxf(hp, 1e-12f));
            float dn = sqrtf(fmaxf(hn, 1e-12f));
            sum += fmaxf(dp - dn + MARGIN, 0.0f);
            cnt += 1.0f;
        }
    }
    ssum[tid] = sum; scnt[tid] = cnt;
    __syncthreads();
    for (int s = 256; s; s >>= 1) {
        if (tid < s) { ssum[tid] += ssum[tid + s]; scnt[tid] += scnt[tid + s]; }
        __syncthreads();
    }
    if (tid == 0) out[0] = ssum[0] / fmaxf(scnt[0], 1.0f);
}

extern "C" void kernel_launch(void* const* d_in, const int* in_sizes, int n_in,
                              void* d_out, int out_size) {
    const float* emb = (const float*)d_in[0];
    const void*  lab = d_in[1];
    float* out = (float*)d_out;

    // cudaFuncSetAttribute is not a stream op; idempotent, capture-safe
    // (also runs during the pre-capture correctness call, so the attribute
    // is already applied before graph capture begins).
    size_t smem = (size_t)(DM * STR * 2 + BN) * sizeof(float) + BN * sizeof(int);
    cudaFuncSetAttribute(k2_gemm_minmax, cudaFuncAttributeMaxDynamicSharedMemorySize, (int)smem);
    (void)in_sizes; (void)n_in; (void)out_size;

    k0_init<<<(BSZ + 255) / 256, 256>>>(lab);
    k1_norm_hist<<<BSZ / 8, 256>>>(emb, lab);          // 8 warps/block, 1 warp/row
    dim3 grid(BSZ / BM, NSLAB);
    k2_gemm_minmax<<<grid, 256, smem>>>(emb, lab);
    k3_reduce<<<1, 512>>>(lab, out);
}

// round 15
// speedup vs baseline: 2.5148x; 2.5148x over previous
#include <cuda_runtime.h>
#include <cuda_bf16.h>
#include <cstdint>

// BatchHardTripletLoss via warp-level bf16 HMMA (mma.sync m16n8k16 — portable
// compute_103; tcgen05 is unavailable because the harness emits PTX at the
// non-'a' virtual arch).
//  k0: init accumulators + hist, detect label dtype
//  k1: row squared norms + label histogram
//  ks: split fp32 embeddings into bf16 hi/lo planes
//  kg: 128x128 Gram tiles; warp-level mma (hi*hi + lo*hi + hi*lo), fused
//      masked max/min epilogue on squared distances (sqrt deferred)
//  k3a/k3b: two-stage mean reduce

#define BSZ   4096
#define DM    128
#define NCLS  512
#define TM    128
#define TN    128
#define BSTR  136        // B smem stride (bf16 elems): 272B rows -> conflict-free, 16B aligned
#define MARGIN 0.3f

__device__ unsigned g_hp[BSZ];
__device__ unsigned g_hn[BSZ];
__device__ float    g_norms[BSZ];
__device__ int      g_hist[NCLS];
__device__ int      g_lab64;
__device__ __nv_bfloat16 g_hi[BSZ * DM];
__device__ __nv_bfloat16 g_lo[BSZ * DM];
__device__ float    g_ps[32];
__device__ float    g_pc[32];

// smem byte offsets (dynamic)
#define SM_BH  0
#define SM_BL  (128 * BSTR * 2)
#define SM_CN  (SM_BL + 128 * BSTR * 2)
#define SM_CL  (SM_CN + 512)
#define SM_TOT (SM_CL + 512)

__device__ __forceinline__ int load_label(const void* lab, int i) {
    if (g_lab64) return (int)((const long long*)lab)[i];
    return ((const int*)lab)[i];
}

// mma.sync m16n8k16 row.col f32.bf16.bf16.f32 (sm_80+ portable)
__device__ __forceinline__ void mma16816(float* c, const uint32_t* a,
                                         uint32_t b0, uint32_t b1) {
    asm volatile(
        "mma.sync.aligned.m16n8k16.row.col.f32.bf16.bf16.f32 "
        "{%0,%1,%2,%3}, {%4,%5,%6,%7}, {%8,%9}, {%0,%1,%2,%3};"
        : "+f"(c[0]), "+f"(c[1]), "+f"(c[2]), "+f"(c[3])
        : "r"(a[0]), "r"(a[1]), "r"(a[2]), "r"(a[3]), "r"(b0), "r"(b1));
}

// ---------------- k0: init ----------------
__global__ void k0_init(const void* __restrict__ lab) {
    int i = blockIdx.x * blockDim.x + threadIdx.x;
    if (i < BSZ) { g_hp[i] = 0u; g_hn[i] = 0x7f800000u; }
    if (i < NCLS) g_hist[i] = 0;
    if (i == 0) {
        const int* w = (const int*)lab;
        int all0 = 1;
        #pragma unroll
        for (int j = 0; j < 64; j++) all0 &= (w[2 * j + 1] == 0);
        g_lab64 = all0;
    }
}

// ---------------- k1: norms + histogram ----------------
__global__ void k1_norm_hist(const float* __restrict__ emb, const void* __restrict__ lab) {
    int warp = (blockIdx.x * blockDim.x + threadIdx.x) >> 5;
    int lane = threadIdx.x & 31;
    if (warp >= BSZ) return;
    float4 v = ((const float4*)(emb + (size_t)warp * DM))[lane];
    float s = v.x * v.x + v.y * v.y + v.z * v.z + v.w * v.w;
    #pragma unroll
    for (int o = 16; o; o >>= 1) s += __shfl_xor_sync(0xffffffffu, s, o);
    if (lane == 0) {
        g_norms[warp] = s;
        atomicAdd(&g_hist[load_label(lab, warp)], 1);
    }
}

// ---------------- ks: bf16 hi/lo split ----------------
__global__ void k_split(const float* __restrict__ emb) {
    int i = blockIdx.x * blockDim.x + threadIdx.x;   // over 131072 float4s
    float4 v = ((const float4*)emb)[i];
    int b = i * 4;
    #pragma unroll
    for (int j = 0; j < 4; j++) {
        float x = (j == 0) ? v.x : (j == 1) ? v.y : (j == 2) ? v.z : v.w;
        __nv_bfloat16 h = __float2bfloat16_rn(x);
        g_hi[b + j] = h;
        g_lo[b + j] = __float2bfloat16_rn(x - __bfloat162float(h));
    }
}

// ---------------- kg: warp-MMA Gram tile + min/max epilogue ----------------
__global__ void __launch_bounds__(256, 1)
kg_gemm(const void* __restrict__ lab) {
    extern __shared__ char sm[];
    __nv_bfloat16* Bh = (__nv_bfloat16*)(sm + SM_BH);
    __nv_bfloat16* Bl = (__nv_bfloat16*)(sm + SM_BL);
    float* cn = (float*)(sm + SM_CN);
    int*   cl = (int*)(sm + SM_CL);

    const int tid = threadIdx.x;
    const int w   = tid >> 5;
    const int lane = tid & 31;
    const int g = lane >> 2;          // group row 0..7
    const int t = lane & 3;           // thread-in-group
    const int col0 = blockIdx.x * TN;
    const int row0 = blockIdx.y * TM;

    // ---- fill B planes into smem: [n][k], stride BSTR ----
    {
        int n = tid >> 1, h = tid & 1;           // 128 rows x 2 halves
        const uint4* srcH = (const uint4*)(g_hi + (size_t)(col0 + n) * DM + 64 * h);
        const uint4* srcL = (const uint4*)(g_lo + (size_t)(col0 + n) * DM + 64 * h);
        uint4* dstH = (uint4*)(Bh + n * BSTR + 64 * h);
        uint4* dstL = (uint4*)(Bl + n * BSTR + 64 * h);
        #pragma unroll
        for (int i = 0; i < 8; i++) { dstH[i] = srcH[i]; dstL[i] = srcL[i]; }
    }
    if (tid < TN) {
        cn[tid] = g_norms[col0 + tid];
        cl[tid] = load_label(lab, col0 + tid);
    }

    // ---- A fragments (this warp's 16 rows, K=128, both planes) from gmem ----
    const int r0 = row0 + w * 16;
    uint32_t Ah[8][4], Al[8][4];
    #pragma unroll
    for (int kc = 0; kc < 8; kc++) {
        int k0 = kc * 16 + 2 * t;
        Ah[kc][0] = *(const uint32_t*)(g_hi + (size_t)(r0 + g)     * DM + k0);
        Ah[kc][1] = *(const uint32_t*)(g_hi + (size_t)(r0 + g + 8) * DM + k0);
        Ah[kc][2] = *(const uint32_t*)(g_hi + (size_t)(r0 + g)     * DM + k0 + 8);
        Ah[kc][3] = *(const uint32_t*)(g_hi + (size_t)(r0 + g + 8) * DM + k0 + 8);
        Al[kc][0] = *(const uint32_t*)(g_lo + (size_t)(r0 + g)     * DM + k0);
        Al[kc][1] = *(const uint32_t*)(g_lo + (size_t)(r0 + g + 8) * DM + k0);
        Al[kc][2] = *(const uint32_t*)(g_lo + (size_t)(r0 + g)     * DM + k0 + 8);
        Al[kc][3] = *(const uint32_t*)(g_lo + (size_t)(r0 + g + 8) * DM + k0 + 8);
    }

    float rn0 = g_norms[r0 + g];
    float rn1 = g_norms[r0 + g + 8];
    int   rl0 = load_label(lab, r0 + g);
    int   rl1 = load_label(lab, r0 + g + 8);

    __syncthreads();

    const float INF = __int_as_float(0x7f800000);
    float pm0 = 0.f, nm0 = INF, pm1 = 0.f, nm1 = INF;

    #pragma unroll
    for (int nc = 0; nc < 16; nc += 2) {
        float c0[4] = {0.f, 0.f, 0.f, 0.f};
        float c1[4] = {0.f, 0.f, 0.f, 0.f};
        // dot = hi*hi + lo*hi + hi*lo (lo*lo negligible)
        #pragma unroll
        for (int p = 0; p < 3; p++) {
            const uint32_t (*A)[4] = (p == 1) ? Al : Ah;
            const __nv_bfloat16* B = (p == 2) ? Bl : Bh;
            #pragma unroll
            for (int kc = 0; kc < 8; kc++) {
                int k0 = kc * 16 + 2 * t;
                const __nv_bfloat16* b_ptr0 = B + (nc * 8 + g) * BSTR + k0;
                const __nv_bfloat16* b_ptr1 = B + ((nc + 1) * 8 + g) * BSTR + k0;
                uint32_t b00 = *(const uint32_t*)(b_ptr0);
                uint32_t b01 = *(const uint32_t*)(b_ptr0 + 8);
                uint32_t b10 = *(const uint32_t*)(b_ptr1);
                uint32_t b11 = *(const uint32_t*)(b_ptr1 + 8);
                mma16816(c0, A[kc], b00, b01);
                mma16816(c1, A[kc], b10, b11);
            }
        }
        // epilogue on squared distances (clamped >= 0); sqrt deferred
        #pragma unroll
        for (int q = 0; q < 2; q++) {
            const float* c = q ? c1 : c0;
            int j0 = (nc + q) * 8 + 2 * t;
            float cn0 = cn[j0], cn1 = cn[j0 + 1];
            int   cl0v = cl[j0], cl1v = cl[j0 + 1];
            float s00 = fmaxf(fmaf(-2.0f, c[0], rn0 + cn0), 0.0f);  // (g,   j0)
            float s01 = fmaxf(fmaf(-2.0f, c[1], rn0 + cn1), 0.0f);  // (g,   j0+1)
            float s10 = fmaxf(fmaf(-2.0f, c[2], rn1 + cn0), 0.0f);  // (g+8, j0)
            float s11 = fmaxf(fmaf(-2.0f, c[3], rn1 + cn1), 0.0f);  // (g+8, j0+1)
            if (rl0 == cl0v) pm0 = fmaxf(pm0, s00); else nm0 = fminf(nm0, s00);
            if (rl0 == cl1v) pm0 = fmaxf(pm0, s01); else nm0 = fminf(nm0, s01);
            if (rl1 == cl0v) pm1 = fmaxf(pm1, s10); else nm1 = fminf(nm1, s10);
            if (rl1 == cl1v) pm1 = fmaxf(pm1, s11); else nm1 = fminf(nm1, s11);
        }
    }

    // reduce across the 4 threads of each group (xor 1, 2)
    #pragma unroll
    for (int o = 1; o < 4; o <<= 1) {
        pm0 = fmaxf(pm0, __shfl_xor_sync(0xffffffffu, pm0, o));
        nm0 = fminf(nm0, __shfl_xor_sync(0xffffffffu, nm0, o));
        pm1 = fmaxf(pm1, __shfl_xor_sync(0xffffffffu, pm1, o));
        nm1 = fminf(nm1, __shfl_xor_sync(0xffffffffu, nm1, o));
    }
    if (t == 0) {
        atomicMax(&g_hp[r0 + g], __float_as_uint(pm0));     // >=0: uint==float order
        atomicMin(&g_hn[r0 + g], __float_as_uint(nm0));
        atomicMax(&g_hp[r0 + g + 8], __float_as_uint(pm1));
        atomicMin(&g_hn[r0 + g + 8], __float_as_uint(nm1));
    }
}

// ---------------- k3a/k3b: two-stage reduce ----------------
__global__ void k3a(const void* __restrict__ lab) {
    __shared__ float ss[128], sc[128];
    int tid = threadIdx.x;
    int r = blockIdx.x * 128 + tid;
    int h = g_hist[load_label(lab, r)];
    float s = 0.f, c = 0.f;
    if (h > 1 && h < BSZ) {
        float dp = sqrtf(fmaxf(__uint_as_float(g_hp[r]), 1e-12f));
        float dn = sqrtf(fmaxf(__uint_as_float(g_hn[r]), 1e-12f));
        s = fmaxf(dp - dn + MARGIN, 0.0f);
        c = 1.f;
    }
    ss[tid] = s; sc[tid] = c;
    __syncthreads();
    for (int o = 64; o; o >>= 1) {
        if (tid < o) { ss[tid] += ss[tid + o]; sc[tid] += sc[tid + o]; }
        __syncthreads();
    }
    if (tid == 0) { g_ps[blockIdx.x] = ss[0]; g_pc[blockIdx.x] = sc[0]; }
}

__global__ void k3b(float* __restrict__ out) {
    int t = threadIdx.x;
    float s = g_ps[t], c = g_pc[t];
    #pragma unroll
    for (int o = 16; o; o >>= 1) {
        s += __shfl_xor_sync(0xffffffffu, s, o);
        c += __shfl_xor_sync(0xffffffffu, c, o);
    }
    if (t == 0) out[0] = s / fmaxf(c, 1.0f);
}

// ---------------- launch ----------------
extern "C" void kernel_launch(void* const* d_in, const int* in_sizes, int n_in,
                              void* d_out, int out_size) {
    const float* emb = (const float*)d_in[0];
    const void*  lab = d_in[1];
    float* out = (float*)d_out;
    (void)in_sizes; (void)n_in; (void)out_size;

    cudaFuncSetAttribute(kg_gemm, cudaFuncAttributeMaxDynamicSharedMemorySize, SM_TOT);

    k0_init<<<16, 256>>>(lab);
    k1_norm_hist<<<BSZ / 8, 256>>>(emb, lab);
    k_split<<<(BSZ * DM / 4) / 256, 256>>>(emb);
    dim3 grid(BSZ / TN, BSZ / TM);
    kg_gemm<<<grid, 256, SM_TOT>>>(lab);
    k3a<<<32, 128>>>(lab);
    k3b<<<1, 32>>>(out);
}